// round 9
// baseline (speedup 1.0000x reference)
#include <cuda_runtime.h>

#define NATOMS 512
#define BATCH  32
#define NN     (NATOMS * NATOMS)
#define INV2PI 0.15915494309189535f
#define NT     16
#define NTILES (NT * (NT + 1) / 2)   // 136

struct F3 { float x, y, z; };

__device__ __forceinline__ F3 f3sub(float4 a, float4 b) { return {a.x - b.x, a.y - b.y, a.z - b.z}; }
__device__ __forceinline__ F3 f3cross(F3 a, F3 b) {
    return {a.y * b.z - a.z * b.y,
            a.z * b.x - a.x * b.z,
            a.x * b.y - a.y * b.x};
}
__device__ __forceinline__ float f3dot(F3 a, F3 b) { return a.x * b.x + a.y * b.y + a.z * b.z; }

__device__ __forceinline__ float rsqrt_a(float x) {
    float r; asm("rsqrt.approx.f32 %0, %1;" : "=f"(r) : "f"(x)); return r;
}
__device__ __forceinline__ float sqrt_a(float x) {
    float r; asm("sqrt.approx.f32 %0, %1;" : "=f"(r) : "f"(x)); return r;
}

// Scalar asin via A&S 4.4.46 (|err|<=2e-8): asin(t) = pi/2 - sqrt(1-t)*P7(t).
// Plain fmaf with literal coefficients -> FFMA-imm (rt_SMSP=1, zero setup).
__device__ __forceinline__ float asin_fast(float x) {
    float t = fminf(fabsf(x), 1.0f);
    float p = fmaf(t, -0.0012624911f, 0.0066700901f);
    p = fmaf(p, t, -0.0170881256f);
    p = fmaf(p, t,  0.0308918810f);
    p = fmaf(p, t, -0.0501743046f);
    p = fmaf(p, t,  0.0889789874f);
    p = fmaf(p, t, -0.2145988016f);
    p = fmaf(p, t,  1.5707963050f);
    float r = fmaf(sqrt_a(1.0f - t), -p, 1.5707963267948966f);
    return copysignf(r, x);
}

// One cell using g = x[j+1]-x[j]:
//   e1 = e0+g, e3 = e2+g  =>  u0 = e0 x g,  u2 = g x e2,  u3 = e2 x e0,
//   u1 = e1 x e3 = u0 + u2 - u3   (cross replaced by adds; e3 never built).
// Carry from cell (i-1,j): e0 = prev e2; u0reg = prev u2 == -(true u0);
// r0 = prev r2. Negations fold into t01/t30 via asin oddness and the sign mask.
template<bool FIRST>
__device__ __forceinline__ float cell_wr(
    float4 P0, float4 P1, F3 g, float4 P2,
    F3& ce2, F3& cu2, float& cr2)
{
    F3 e0;
    if (FIRST) e0 = f3sub(P2, P0);
    else       e0 = ce2;
    F3 e2 = f3sub(P2, P1);

    F3 u0; float r0;
    if (FIRST) {
        u0 = f3cross(e0, g);
        r0 = rsqrt_a(f3dot(u0, u0));
    } else {
        u0 = cu2;            // == -(true u0)
        r0 = cr2;
    }

    F3 u2 = f3cross(g, e2);
    F3 u3 = f3cross(e2, e0);

    F3 u1; // true u1 = u0_true + u2 - u3
    if (FIRST) u1 = { u0.x + u2.x - u3.x, u0.y + u2.y - u3.y, u0.z + u2.z - u3.z };
    else       u1 = { u2.x - u3.x - u0.x, u2.y - u3.y - u0.y, u2.z - u3.z - u0.z };

    float r1 = rsqrt_a(f3dot(u1, u1));
    float r2 = rsqrt_a(f3dot(u2, u2));
    float r3 = rsqrt_a(f3dot(u3, u3));

    float d01 = f3dot(u0, u1);
    float d12 = f3dot(u1, u2);
    float d23 = f3dot(u2, u3);
    float d30 = f3dot(u3, u0);

    float t01, t30;
    if (FIRST) {
        t01 = d01 * (r0 * r1);
        t30 = d30 * (r3 * r0);
    } else {
        t01 = -(d01 * (r0 * r1));
        t30 = -(d30 * (r3 * r0));
    }
    float t12 = d12 * (r1 * r2);
    float t23 = d23 * (r2 * r3);

    float om = ((asin_fast(t01) + asin_fast(t12)) +
                (asin_fast(t23) + asin_fast(t30))) * INV2PI;

    // true sv = -(u0_true . e2); carried u0reg is already negated.
    float dsv = f3dot(u0, e2);
    unsigned smask;
    if (FIRST)
        smask = (__float_as_uint(dsv) ^ 0x80000000u) & 0x80000000u;
    else
        smask = __float_as_uint(dsv) & 0x80000000u;
    float wr = __uint_as_float(__float_as_uint(om) ^ smask);

    ce2 = e2; cu2 = u2; cr2 = r2;
    return wr;
}

// Segment set: {(i,j): 0<=i<=509, i+2<=j<=510}. Final scatter state:
// every (i,j) owns out[i+1][j+1] (+mirror); i==0 also keeps out[0][j] (+mirror).
// Never-written cells (|r-c|<=1 band, (0,511),(511,0)) zeroed by diagonal tiles.
// 128 threads/block: lane tx = j offset, warp ty (0..3) covers 8 consecutive i.
__global__ __launch_bounds__(128) void writhe_tile_kernel(
    const float* __restrict__ x,
    float*       __restrict__ out)
{
    __shared__ float4 si[33];
    __shared__ float4 sj4[33];
    __shared__ float  smwr[32][33];

    // Closed-form decode of k -> (ti, tj), row ti has 16-ti entries.
    const int k = blockIdx.x;
    int ti = (int)((33.0f - sqrtf((float)(1089 - 8 * k))) * 0.5f);
    if (k < ti * (33 - ti) / 2) ti--;
    else if (k >= (ti + 1) * (32 - ti) / 2) ti++;
    const int tj = ti + (k - ti * (33 - ti) / 2);
    const int i0 = ti * 32, j0 = tj * 32;
    const bool fastTile = (ti >= 1) && (tj >= ti + 2) && (tj <= 14);

    const int b = blockIdx.y;
    const float* xb = x + (size_t)b * (NATOMS * 3);
    float* ob = out + (size_t)b * NN;

    const int tx = threadIdx.x & 31;
    const int ty = threadIdx.x >> 5;    // 0..3

    {
        int t = threadIdx.x;
        if (t < 66) {
            int local = (t < 33) ? t : t - 33;
            int c = min(((t < 33) ? i0 : j0) + local, NATOMS - 1);
            float4 v = make_float4(xb[3 * c], xb[3 * c + 1], xb[3 * c + 2], 0.f);
            if (t < 33) si[local] = v; else sj4[local] = v;
        }
    }
    if (ty == 1 && ti == tj) {
        int r = i0 + tx;
        ob[r * 513] = 0.f;
        if (r < NATOMS - 1) { ob[r * 513 + 1] = 0.f; ob[r * 513 + 512] = 0.f; }
        if (ti == 0 && tx == 0) { ob[NATOMS - 1] = 0.f; ob[(NATOMS - 1) * NATOMS] = 0.f; }
    }
    __syncthreads();

    const int j = j0 + tx;
    const float4 P2 = sj4[tx];
    const float4 P3 = sj4[tx + 1];
    const F3 g = f3sub(P3, P2);          // x[j+1]-x[j], per-thread constant
    const int ibase = 8 * ty;            // 8 consecutive i per thread

    F3 ce2, cu2;
    float cr2;
    float wrv[8];

    #pragma unroll
    for (int kk = 0; kk < 8; kk++) {
        const int ii = ibase + kk;
        const float4 P0 = si[ii];
        const float4 P1 = si[ii + 1];
        float wr = (kk == 0)
            ? cell_wr<true >(P0, P1, g, P2, ce2, cu2, cr2)
            : cell_wr<false>(P0, P1, g, P2, ce2, cu2, cr2);
        smwr[ii][tx] = wr;
        wrv[kk] = wr;
    }

    if (fastTile) {
        float* orow = ob + (size_t)(i0 + ibase + 1) * NATOMS + (j + 1);
        #pragma unroll
        for (int kk = 0; kk < 8; kk++)
            orow[kk * NATOMS] = wrv[kk];
    } else {
        #pragma unroll
        for (int kk = 0; kk < 8; kk++) {
            const int i = i0 + ibase + kk;
            bool valid = (j >= i + 2) && (i <= NATOMS - 3) && (j <= NATOMS - 2);
            if (valid) {
                ob[(i + 1) * NATOMS + (j + 1)] = wrv[kk];
                if (i == 0) {
                    ob[j] = wrv[kk];              // (0, j) first-scatter survivor
                    ob[j * NATOMS] = wrv[kk];     // (j, 0)
                }
            }
        }
    }
    __syncthreads();

    // Mirror: coalesced out[j+1][i+1] via transposed smem reads (stride 33).
    if (fastTile) {
        float* ocol = ob + (size_t)(j0 + ibase + 1) * NATOMS + (i0 + tx + 1);
        #pragma unroll
        for (int kk = 0; kk < 8; kk++)
            ocol[kk * NATOMS] = smwr[tx][ibase + kk];
    } else {
        #pragma unroll
        for (int kk = 0; kk < 8; kk++) {
            const int jj = ibase + kk;
            const int jm = j0 + jj;
            const int im = i0 + tx;
            float v = smwr[tx][jj];
            bool valid = (jm >= im + 2) && (im <= NATOMS - 3) && (jm <= NATOMS - 2);
            if (valid)
                ob[(jm + 1) * NATOMS + (im + 1)] = v;
        }
    }
}

extern "C" void kernel_launch(void* const* d_in, const int* in_sizes, int n_in,
                              void* d_out, int out_size)
{
    int xi = (in_sizes[0] == BATCH * NATOMS * 3) ? 0 : 1;
    const float* x   = (const float*)d_in[xi];
    float*       out = (float*)d_out;

    dim3 grid(NTILES, BATCH);
    writhe_tile_kernel<<<grid, 128>>>(x, out);
}

// round 10
// speedup vs baseline: 1.0707x; 1.0707x over previous
#include <cuda_runtime.h>

#define NATOMS 512
#define BATCH  32
#define NN     (NATOMS * NATOMS)
#define NT     16
#define NTILES (NT * (NT + 1) / 2)   // 136

typedef unsigned long long u64;

struct F3 { float x, y, z; };

__device__ __forceinline__ F3 f3sub(float4 a, float4 b) { return {a.x - b.x, a.y - b.y, a.z - b.z}; }
__device__ __forceinline__ F3 f3cross(F3 a, F3 b) {
    return {a.y * b.z - a.z * b.y,
            a.z * b.x - a.x * b.z,
            a.x * b.y - a.y * b.x};
}
__device__ __forceinline__ float f3dot(F3 a, F3 b) { return a.x * b.x + a.y * b.y + a.z * b.z; }

__device__ __forceinline__ float rsqrt_a(float x) {
    float r; asm("rsqrt.approx.f32 %0, %1;" : "=f"(r) : "f"(x)); return r;
}
__device__ __forceinline__ float sqrt_a(float x) {
    float r; asm("sqrt.approx.f32 %0, %1;" : "=f"(r) : "f"(x)); return r;
}

// ---- packed f32x2 helpers (non-volatile: CSE-able) ----
__device__ __forceinline__ u64 pk2(float lo, float hi) {
    u64 r; asm("mov.b64 %0, {%1, %2};" : "=l"(r) : "f"(lo), "f"(hi)); return r;
}
__device__ __forceinline__ void upk2(u64 v, float& lo, float& hi) {
    asm("mov.b64 {%0, %1}, %2;" : "=f"(lo), "=f"(hi) : "l"(v));
}
__device__ __forceinline__ u64 fma2(u64 a, u64 b, u64 c) {
    u64 d; asm("fma.rn.f32x2 %0, %1, %2, %3;" : "=l"(d) : "l"(a), "l"(b), "l"(c)); return d;
}

// Paired scaled asin: returns asin(x)/(2*pi). A&S 4.4.46 with all coefficients
// and the pi/2 constants pre-multiplied by 1/(2*pi)  (|err| <= 2e-8 / 2pi).
__device__ __forceinline__ void asin2pi_fast(float xa, float xb, float& ra, float& rb) {
    float ta = fminf(fabsf(xa), 1.0f);
    float tb = fminf(fabsf(xb), 1.0f);
    float sa = 1.0f - ta;
    float sb = 1.0f - tb;

    u64 t2 = pk2(ta, tb);
    u64 p  = pk2(-2.0092277e-4f, -2.0092277e-4f);
    p = fma2(p, t2, pk2( 1.0615793e-3f,  1.0615793e-3f));
    p = fma2(p, t2, pk2(-2.7196690e-3f, -2.7196690e-3f));
    p = fma2(p, t2, pk2( 4.9166075e-3f,  4.9166075e-3f));
    p = fma2(p, t2, pk2(-7.9855286e-3f, -7.9855286e-3f));
    p = fma2(p, t2, pk2( 1.4161419e-2f,  1.4161419e-2f));
    p = fma2(p, t2, pk2(-3.4156516e-2f, -3.4156516e-2f));
    p = fma2(p, t2, pk2( 2.4999999e-1f,  2.4999999e-1f));

    float pa, pb;
    upk2(p, pa, pb);
    float qa = fmaf(sqrt_a(sa), -pa, 0.25f);
    float qb = fmaf(sqrt_a(sb), -pb, 0.25f);
    ra = copysignf(qa, xa);
    rb = copysignf(qb, xb);
}

// One cell using g = x[j+1]-x[j]:
//   e1 = e0+g, e3 = e2+g  =>  u0 = e0 x g,  u2 = g x e2,  u3 = e2 x e0,
//   u1 = e1 x e3 = u0 + u2 - u3   (cross replaced by adds; e3 never built).
// Carry from cell (i-1,j): e0 = prev e2; u0reg = prev u2 == -(true u0);
// r0 = prev r2. Negations fold into t01/t30 via asin oddness and the sign mask.
template<bool FIRST>
__device__ __forceinline__ float cell_wr(
    F3 e0in, float4 P1, F3 g, float4 P2,
    F3& ce2, F3& cu2, float& cr2)
{
    F3 e0;
    if (FIRST) e0 = e0in;
    else       e0 = ce2;
    F3 e2 = f3sub(P2, P1);

    F3 u0; float r0;
    if (FIRST) {
        u0 = f3cross(e0, g);
        r0 = rsqrt_a(f3dot(u0, u0));
    } else {
        u0 = cu2;            // == -(true u0)
        r0 = cr2;
    }

    F3 u2 = f3cross(g, e2);
    F3 u3 = f3cross(e2, e0);

    F3 u1; // true u1 = u0_true + u2 - u3
    if (FIRST) u1 = { u0.x + u2.x - u3.x, u0.y + u2.y - u3.y, u0.z + u2.z - u3.z };
    else       u1 = { u2.x - u3.x - u0.x, u2.y - u3.y - u0.y, u2.z - u3.z - u0.z };

    float r1 = rsqrt_a(f3dot(u1, u1));
    float r2 = rsqrt_a(f3dot(u2, u2));
    float r3 = rsqrt_a(f3dot(u3, u3));

    float d01 = f3dot(u0, u1);
    float d12 = f3dot(u1, u2);
    float d23 = f3dot(u2, u3);
    float d30 = f3dot(u3, u0);

    float t01, t30;
    if (FIRST) {
        t01 = d01 * (r0 * r1);
        t30 = d30 * (r3 * r0);
    } else {
        t01 = -(d01 * (r0 * r1));
        t30 = -(d30 * (r3 * r0));
    }
    float t12 = d12 * (r1 * r2);
    float t23 = d23 * (r2 * r3);

    float a01, a12, a23, a30;
    asin2pi_fast(t01, t12, a01, a12);
    asin2pi_fast(t23, t30, a23, a30);
    float om = (a01 + a12) + (a23 + a30);   // already scaled by 1/2pi

    // true sv = -(u0_true . e2); carried u0reg is already negated.
    float dsv = f3dot(u0, e2);
    unsigned smask;
    if (FIRST)
        smask = (__float_as_uint(dsv) ^ 0x80000000u) & 0x80000000u;
    else
        smask = __float_as_uint(dsv) & 0x80000000u;
    float wr = __uint_as_float(__float_as_uint(om) ^ smask);

    ce2 = e2; cu2 = u2; cr2 = r2;
    return wr;
}

// Segment set: {(i,j): 0<=i<=509, i+2<=j<=510}. Final scatter state:
// every (i,j) owns out[i+1][j+1] (+mirror); i==0 also keeps out[0][j] (+mirror).
// Never-written cells (|r-c|<=1 band, (0,511),(511,0)) zeroed by diagonal tiles.
// 128 threads/block: lane tx = j offset, warp ty (0..3) covers 8 consecutive i.
__global__ __launch_bounds__(128, 12) void writhe_tile_kernel(
    const float* __restrict__ x,
    float*       __restrict__ out)
{
    __shared__ float4 si[33];
    __shared__ float4 sj4[33];
    __shared__ float  smwr[32][33];

    // Closed-form decode of k -> (ti, tj), row ti has 16-ti entries.
    const int k = blockIdx.x;
    int ti = (int)((33.0f - sqrtf((float)(1089 - 8 * k))) * 0.5f);
    if (k < ti * (33 - ti) / 2) ti--;
    else if (k >= (ti + 1) * (32 - ti) / 2) ti++;
    const int tj = ti + (k - ti * (33 - ti) / 2);
    const int i0 = ti * 32, j0 = tj * 32;
    const bool fastTile = (ti >= 1) && (tj >= ti + 2) && (tj <= 14);

    const int b = blockIdx.y;
    const float* xb = x + (size_t)b * (NATOMS * 3);
    float* ob = out + (size_t)b * NN;

    const int tx = threadIdx.x & 31;
    const int ty = threadIdx.x >> 5;    // 0..3

    {
        int t = threadIdx.x;
        if (t < 66) {
            int local = (t < 33) ? t : t - 33;
            int c = min(((t < 33) ? i0 : j0) + local, NATOMS - 1);
            float4 v = make_float4(xb[3 * c], xb[3 * c + 1], xb[3 * c + 2], 0.f);
            if (t < 33) si[local] = v; else sj4[local] = v;
        }
    }
    if (ty == 1 && ti == tj) {
        int r = i0 + tx;
        ob[r * 513] = 0.f;
        if (r < NATOMS - 1) { ob[r * 513 + 1] = 0.f; ob[r * 513 + 512] = 0.f; }
        if (ti == 0 && tx == 0) { ob[NATOMS - 1] = 0.f; ob[(NATOMS - 1) * NATOMS] = 0.f; }
    }
    __syncthreads();

    const int j = j0 + tx;
    const float4 P2 = sj4[tx];
    const float4 P3 = sj4[tx + 1];
    const F3 g = f3sub(P3, P2);          // x[j+1]-x[j], per-thread constant
    const int ibase = 8 * ty;            // 8 consecutive i per thread

    F3 ce2, cu2;
    float cr2;
    float wrv[8];

    // Cell 0 peeled: only place si[ibase] (P0) is needed.
    {
        F3 e00 = f3sub(P2, si[ibase]);
        wrv[0] = cell_wr<true>(e00, si[ibase + 1], g, P2, ce2, cu2, cr2);
        smwr[ibase][tx] = wrv[0];
    }
    #pragma unroll
    for (int kk = 1; kk < 8; kk++) {
        const int ii = ibase + kk;
        wrv[kk] = cell_wr<false>(F3{0.f, 0.f, 0.f}, si[ii + 1], g, P2, ce2, cu2, cr2);
        smwr[ii][tx] = wrv[kk];
    }

    if (fastTile) {
        float* orow = ob + (size_t)(i0 + ibase + 1) * NATOMS + (j + 1);
        #pragma unroll
        for (int kk = 0; kk < 8; kk++)
            orow[kk * NATOMS] = wrv[kk];
    } else {
        #pragma unroll
        for (int kk = 0; kk < 8; kk++) {
            const int i = i0 + ibase + kk;
            bool valid = (j >= i + 2) && (i <= NATOMS - 3) && (j <= NATOMS - 2);
            if (valid) {
                ob[(i + 1) * NATOMS + (j + 1)] = wrv[kk];
                if (i == 0) {
                    ob[j] = wrv[kk];              // (0, j) first-scatter survivor
                    ob[j * NATOMS] = wrv[kk];     // (j, 0)
                }
            }
        }
    }
    __syncthreads();

    // Mirror: coalesced out[j+1][i+1] via transposed smem reads (stride 33).
    if (fastTile) {
        float* ocol = ob + (size_t)(j0 + ibase + 1) * NATOMS + (i0 + tx + 1);
        #pragma unroll
        for (int kk = 0; kk < 8; kk++)
            ocol[kk * NATOMS] = smwr[tx][ibase + kk];
    } else {
        #pragma unroll
        for (int kk = 0; kk < 8; kk++) {
            const int jj = ibase + kk;
            const int jm = j0 + jj;
            const int im = i0 + tx;
            float v = smwr[tx][jj];
            bool valid = (jm >= im + 2) && (im <= NATOMS - 3) && (jm <= NATOMS - 2);
            if (valid)
                ob[(jm + 1) * NATOMS + (im + 1)] = v;
        }
    }
}

extern "C" void kernel_launch(void* const* d_in, const int* in_sizes, int n_in,
                              void* d_out, int out_size)
{
    int xi = (in_sizes[0] == BATCH * NATOMS * 3) ? 0 : 1;
    const float* x   = (const float*)d_in[xi];
    float*       out = (float*)d_out;

    dim3 grid(NTILES, BATCH);
    writhe_tile_kernel<<<grid, 128>>>(x, out);
}